// round 5
// baseline (speedup 1.0000x reference)
#include <cuda_runtime.h>
#include <math.h>

#define B_    16
#define C_    256
#define HIDE_ 128
#define HW_   16384
#define HW4_  4096            // float4 per row
#define ROWS_ (B_*C_)         // 4096

__device__ float g_mean[ROWS_];
__device__ float g_gate[ROWS_];
__device__ int   g_cnt[B_];        // reduce arrivals (zero-init, self-reset)
__device__ int   g_done[B_];       // scale completions (zero-init, self-reset)
__device__ volatile int g_flag[B_];// gate-ready flags (zero-init, self-reset)

__global__ void __launch_bounds__(256, 3)
k_fused(const float* __restrict__ x,
        const float* __restrict__ w1,
        const float* __restrict__ w2p,
        const float* __restrict__ w3p,
        const float* __restrict__ w4,
        const float* __restrict__ A2,
        float* __restrict__ out) {
    extern __shared__ __align__(16) float4 buf[];   // HW4_ float4 = 64 KB (row cache)
    __shared__ __align__(16) float mean_s[C_];
    __shared__ __align__(16) float y_s[HIDE_];
    __shared__ __align__(16) float z_s[HIDE_];
    __shared__ __align__(16) float red[256];
    __shared__ float sm[8];
    __shared__ int   last_s;

    const int row = blockIdx.x;
    const int b   = row >> 8;        // 256 channels per batch
    const int t   = threadIdx.x;

    // ---- Phase 1: load row into smem + reduce to mean ----
    const float4* xr = reinterpret_cast<const float4*>(x) + (size_t)row * HW4_;
    float s = 0.f;
    #pragma unroll
    for (int i = 0; i < 16; ++i) {
        int idx = t + i * 256;
        float4 v = __ldcs(&xr[idx]);
        buf[idx] = v;
        s += (v.x + v.y) + (v.z + v.w);
    }
    #pragma unroll
    for (int off = 16; off > 0; off >>= 1)
        s += __shfl_down_sync(0xffffffffu, s, off);
    int lane = t & 31, wid = t >> 5;
    if (lane == 0) sm[wid] = s;
    __syncthreads();
    if (t == 0) {
        float tot = 0.f;
        #pragma unroll
        for (int w = 0; w < 8; ++w) tot += sm[w];
        g_mean[row] = tot * (1.0f / (float)HW_);
        __threadfence();
        int old = atomicAdd(&g_cnt[b], 1);
        last_s = (old == C_ - 1);
    }
    __syncthreads();

    // ---- Phase 2: last CTA of the batch computes the 256-wide gate ----
    if (last_s) {
        __threadfence();  // acquire: all g_mean writes for batch b visible
        mean_s[t] = __ldcg(&g_mean[b * C_ + t]);
        __syncthreads();

        const float w2 = *w2p;
        const float w3 = *w3p;

        if (t < HIDE_) {
            const float4* wr = reinterpret_cast<const float4*>(w1 + (size_t)t * C_);
            const float4* ms = reinterpret_cast<const float4*>(mean_s);
            float acc = 0.f;
            #pragma unroll 16
            for (int k = 0; k < C_ / 4; ++k) {
                float4 w = wr[k];
                float4 m = ms[k];
                acc = fmaf(m.x, w.x, acc);
                acc = fmaf(m.y, w.y, acc);
                acc = fmaf(m.z, w.z, acc);
                acc = fmaf(m.w, w.w, acc);
            }
            y_s[t] = acc;
        }
        __syncthreads();

        // softmax over HIDE of (w2 * y)
        float v = (t < HIDE_) ? w2 * y_s[t] : -INFINITY;
        red[t] = v;
        __syncthreads();
        #pragma unroll
        for (int off = 128; off > 0; off >>= 1) {
            if (t < off) red[t] = fmaxf(red[t], red[t + off]);
            __syncthreads();
        }
        float m = red[0];
        __syncthreads();
        float e = (t < HIDE_) ? __expf(v - m) : 0.f;
        red[t] = e;
        __syncthreads();
        #pragma unroll
        for (int off = 128; off > 0; off >>= 1) {
            if (t < off) red[t] += red[t + off];
            __syncthreads();
        }
        float inv_sum = 1.0f / red[0];
        __syncthreads();

        if (t < HIDE_) {
            float acc = 0.f;
            #pragma unroll 8
            for (int k = 0; k < HIDE_; ++k) acc = fmaf(y_s[k], A2[(size_t)k * HIDE_ + t], acc);
            float y2 = y_s[t] * (e * inv_sum) + acc;
            z_s[t] = fmaxf(w3 * y2, 0.f);
        }
        __syncthreads();

        {
            const float4* wr = reinterpret_cast<const float4*>(w4 + (size_t)t * HIDE_);
            const float4* zs = reinterpret_cast<const float4*>(z_s);
            float acc = 0.f;
            #pragma unroll 16
            for (int k = 0; k < HIDE_ / 4; ++k) {
                float4 w = wr[k];
                float4 z = zs[k];
                acc = fmaf(z.x, w.x, acc);
                acc = fmaf(z.y, w.y, acc);
                acc = fmaf(z.z, w.z, acc);
                acc = fmaf(z.w, w.w, acc);
            }
            g_gate[b * C_ + t] = 1.0f / (1.0f + __expf(-acc));
        }
        __syncthreads();
        if (t == 0) {
            __threadfence();          // release: gate values before flag
            g_flag[b] = 1;
        }
    }

    // ---- Phase 3: wait for gate, scale smem copy, store out ----
    if (t == 0) {
        while (g_flag[b] == 0) __nanosleep(64);
        __threadfence();              // acquire before reading g_gate
    }
    __syncthreads();

    float g = __ldcg(&g_gate[row]);
    float4* o4 = reinterpret_cast<float4*>(out) + (size_t)row * HW4_;
    #pragma unroll
    for (int i = 0; i < 16; ++i) {
        int idx = t + i * 256;
        float4 v = buf[idx];
        v.x *= g; v.y *= g; v.z *= g; v.w *= g;
        __stcs(&o4[idx], v);
    }

    // ---- Phase 4: self-reset counters (last scaler of the batch) ----
    if (t == 0) {
        __threadfence();
        int old = atomicAdd(&g_done[b], 1);
        if (old == C_ - 1) {
            g_done[b] = 0;
            g_cnt[b]  = 0;
            g_flag[b] = 0;
        }
    }
}

extern "C" void kernel_launch(void* const* d_in, const int* in_sizes, int n_in,
                              void* d_out, int out_size) {
    const float* x  = (const float*)d_in[0];
    const float* w1 = (const float*)d_in[1];
    const float* w2 = (const float*)d_in[2];
    const float* w3 = (const float*)d_in[3];
    const float* w4 = (const float*)d_in[4];
    const float* A2 = (const float*)d_in[5];
    float* out = (float*)d_out;

    static bool attr_set = false;
    if (!attr_set) {
        cudaFuncSetAttribute(k_fused, cudaFuncAttributeMaxDynamicSharedMemorySize,
                             HW4_ * sizeof(float4));
        attr_set = true;
    }
    k_fused<<<ROWS_, 256, HW4_ * sizeof(float4)>>>(x, w1, w2, w3, w4, A2, out);
}

// round 6
// speedup vs baseline: 1.3747x; 1.3747x over previous
#include <cuda_runtime.h>
#include <math.h>

#define B_    16
#define C_    256
#define HIDE_ 128
#define HW_   16384
#define HW4_  4096            // float4 per row
#define ROWS_ (B_*C_)         // 4096

__device__ float g_mean[ROWS_];
__device__ float g_gate[ROWS_];
__device__ int   g_cnt[B_];         // reduce arrivals (zero-init, self-reset)
__device__ int   g_done[B_];        // completions (zero-init, self-reset)
__device__ volatile int g_flag[B_]; // gate-ready flags (zero-init, self-reset)

__global__ void __launch_bounds__(256)
k_fused(const float* __restrict__ x,
        const float* __restrict__ w1,
        const float* __restrict__ w2p,
        const float* __restrict__ w3p,
        const float* __restrict__ w4,
        const float* __restrict__ A2,
        float* __restrict__ out) {
    __shared__ __align__(16) float mean_s[C_];
    __shared__ __align__(16) float y_s[HIDE_];
    __shared__ __align__(16) float z_s[HIDE_];
    __shared__ __align__(16) float red[256];
    __shared__ float sm[8];
    __shared__ int   last_s;

    const int row = blockIdx.x;
    const int b   = row >> 8;        // 256 channels per batch
    const int t   = threadIdx.x;

    // ---- Phase 1: reduce this row to its mean (loads cache in L2) ----
    const float4* xr = reinterpret_cast<const float4*>(x) + (size_t)row * HW4_;
    float s = 0.f;
    #pragma unroll
    for (int i = 0; i < 16; ++i) {
        float4 v = __ldcg(&xr[t + i * 256]);
        s += (v.x + v.y) + (v.z + v.w);
    }
    #pragma unroll
    for (int off = 16; off > 0; off >>= 1)
        s += __shfl_down_sync(0xffffffffu, s, off);
    int lane = t & 31, wid = t >> 5;
    if (lane == 0) sm[wid] = s;
    __syncthreads();
    if (t == 0) {
        float tot = 0.f;
        #pragma unroll
        for (int w = 0; w < 8; ++w) tot += sm[w];
        g_mean[row] = tot * (1.0f / (float)HW_);
        __threadfence();
        int old = atomicAdd(&g_cnt[b], 1);
        last_s = (old == C_ - 1);
    }
    __syncthreads();

    // ---- Phase 2: last CTA of the batch computes the 256-wide gate ----
    if (last_s) {
        __threadfence();  // acquire: all g_mean writes for batch b visible
        mean_s[t] = __ldcg(&g_mean[b * C_ + t]);
        __syncthreads();

        const float w2 = *w2p;
        const float w3 = *w3p;

        if (t < HIDE_) {
            const float4* wr = reinterpret_cast<const float4*>(w1 + (size_t)t * C_);
            const float4* ms = reinterpret_cast<const float4*>(mean_s);
            float acc = 0.f;
            #pragma unroll 16
            for (int k = 0; k < C_ / 4; ++k) {
                float4 w = wr[k];
                float4 m = ms[k];
                acc = fmaf(m.x, w.x, acc);
                acc = fmaf(m.y, w.y, acc);
                acc = fmaf(m.z, w.z, acc);
                acc = fmaf(m.w, w.w, acc);
            }
            y_s[t] = acc;
        }
        __syncthreads();

        // softmax over HIDE of (w2 * y)
        float v = (t < HIDE_) ? w2 * y_s[t] : -INFINITY;
        red[t] = v;
        __syncthreads();
        #pragma unroll
        for (int off = 128; off > 0; off >>= 1) {
            if (t < off) red[t] = fmaxf(red[t], red[t + off]);
            __syncthreads();
        }
        float m = red[0];
        __syncthreads();
        float e = (t < HIDE_) ? __expf(v - m) : 0.f;
        red[t] = e;
        __syncthreads();
        #pragma unroll
        for (int off = 128; off > 0; off >>= 1) {
            if (t < off) red[t] += red[t + off];
            __syncthreads();
        }
        float inv_sum = 1.0f / red[0];
        __syncthreads();

        if (t < HIDE_) {
            float acc = 0.f;
            #pragma unroll 8
            for (int k = 0; k < HIDE_; ++k) acc = fmaf(y_s[k], A2[(size_t)k * HIDE_ + t], acc);
            float y2 = y_s[t] * (e * inv_sum) + acc;
            z_s[t] = fmaxf(w3 * y2, 0.f);
        }
        __syncthreads();

        {
            const float4* wr = reinterpret_cast<const float4*>(w4 + (size_t)t * HIDE_);
            const float4* zs = reinterpret_cast<const float4*>(z_s);
            float acc = 0.f;
            #pragma unroll 16
            for (int k = 0; k < HIDE_ / 4; ++k) {
                float4 w = wr[k];
                float4 z = zs[k];
                acc = fmaf(z.x, w.x, acc);
                acc = fmaf(z.y, w.y, acc);
                acc = fmaf(z.z, w.z, acc);
                acc = fmaf(z.w, w.w, acc);
            }
            g_gate[b * C_ + t] = 1.0f / (1.0f + __expf(-acc));
        }
        __syncthreads();
        if (t == 0) {
            __threadfence();          // release: gate values before flag
            g_flag[b] = 1;
        }
    }

    // ---- Phase 3: wait for gate, re-read row (L2-resident), scale, store ----
    if (t == 0) {
        while (g_flag[b] == 0) __nanosleep(32);
        __threadfence();              // acquire before reading g_gate
    }
    __syncthreads();

    float g = __ldcg(&g_gate[row]);
    float4* o4 = reinterpret_cast<float4*>(out) + (size_t)row * HW4_;
    #pragma unroll
    for (int i = 0; i < 16; ++i) {
        int idx = t + i * 256;
        float4 v = __ldcg(&xr[idx]);      // expected L2 hit
        v.x *= g; v.y *= g; v.z *= g; v.w *= g;
        __stcs(&o4[idx], v);              // evict-first: don't displace x
    }

    // ---- Phase 4: self-reset counters (last finisher of the batch) ----
    if (t == 0) {
        __threadfence();
        int old = atomicAdd(&g_done[b], 1);
        if (old == C_ - 1) {
            g_done[b] = 0;
            g_cnt[b]  = 0;
            g_flag[b] = 0;
        }
    }
}

extern "C" void kernel_launch(void* const* d_in, const int* in_sizes, int n_in,
                              void* d_out, int out_size) {
    const float* x  = (const float*)d_in[0];
    const float* w1 = (const float*)d_in[1];
    const float* w2 = (const float*)d_in[2];
    const float* w3 = (const float*)d_in[3];
    const float* w4 = (const float*)d_in[4];
    const float* A2 = (const float*)d_in[5];
    float* out = (float*)d_out;

    k_fused<<<ROWS_, 256>>>(x, w1, w2, w3, w4, A2, out);
}

// round 8
// speedup vs baseline: 1.9981x; 1.4535x over previous
#include <cuda_runtime.h>
#include <math.h>

#define B_    16
#define C_    256
#define HIDE_ 128
#define HW_   16384
#define HW4_  4096            // float4 per row
#define ROWS_ (B_*C_)         // 4096
#define LAG_  2               // scale(b) dispatched after reduce(b+LAG_)

__device__ float g_mean[ROWS_];
__device__ float g_gate[ROWS_];
__device__ int   g_cnt[B_];          // reduce arrivals  (zero-init, self-reset)
__device__ int   g_done[B_];         // scale arrivals   (zero-init, self-reset)
__device__ volatile int g_flag[B_];  // gate ready       (zero-init, self-reset)

// Grid layout (8192 CTAs total), groups of work in bid order:
//   g = 0,1           : 256 reduce CTAs (batch g)
//   g = 2..15         : 256 reduce CTAs (batch g) + 256 scale CTAs (batch g-2)
//   g = 16,17         : 256 scale CTAs (batch g-2)
__global__ void __launch_bounds__(256)
k_pipe(const float* __restrict__ x,
       const float* __restrict__ w1,
       const float* __restrict__ w2p,
       const float* __restrict__ w3p,
       const float* __restrict__ w4,
       const float* __restrict__ A2,
       float* __restrict__ out) {
    const int bid = blockIdx.x;
    const int t   = threadIdx.x;

    bool is_reduce;
    int b, r;   // batch, row-within-batch
    if (bid < LAG_ * C_) {                       // leading reduce-only groups
        is_reduce = true;  b = bid >> 8;  r = bid & 255;
    } else if (bid < LAG_ * C_ + (B_ - LAG_) * 2 * C_) {   // mixed groups
        int q = bid - LAG_ * C_;
        int gg = q >> 9;            // 0..13
        int within = q & 511;
        if (within < C_) { is_reduce = true;  b = gg + LAG_;  r = within; }
        else             { is_reduce = false; b = gg;         r = within - C_; }
    } else {                                     // trailing scale-only groups
        int q = bid - (LAG_ * C_ + (B_ - LAG_) * 2 * C_);
        is_reduce = false;  b = (B_ - LAG_) + (q >> 8);  r = q & 255;
    }
    const int row = b * C_ + r;

    if (is_reduce) {
        // ---------------- reduce row; last CTA per batch computes gate ----------------
        __shared__ __align__(16) float mean_s[C_];
        __shared__ __align__(16) float y_s[HIDE_];
        __shared__ __align__(16) float z_s[HIDE_];
        __shared__ __align__(16) float red[256];
        __shared__ float sm[8];
        __shared__ int   last_s;

        const float4* xr = reinterpret_cast<const float4*>(x) + (size_t)row * HW4_;
        float s = 0.f;
        #pragma unroll
        for (int i = 0; i < 16; ++i) {
            float4 v = xr[t + i * 256];
            s += (v.x + v.y) + (v.z + v.w);
        }
        #pragma unroll
        for (int off = 16; off > 0; off >>= 1)
            s += __shfl_down_sync(0xffffffffu, s, off);
        int lane = t & 31, wid = t >> 5;
        if (lane == 0) sm[wid] = s;
        __syncthreads();
        if (t == 0) {
            float tot = 0.f;
            #pragma unroll
            for (int w = 0; w < 8; ++w) tot += sm[w];
            g_mean[row] = tot * (1.0f / (float)HW_);
            __threadfence();
            int old = atomicAdd(&g_cnt[b], 1);
            last_s = (old == C_ - 1);
        }
        __syncthreads();
        if (!last_s) return;

        // gate for batch b
        __threadfence();
        mean_s[t] = __ldcg(&g_mean[b * C_ + t]);
        __syncthreads();

        const float w2 = *w2p;
        const float w3 = *w3p;

        if (t < HIDE_) {
            const float4* wr = reinterpret_cast<const float4*>(w1 + (size_t)t * C_);
            const float4* ms = reinterpret_cast<const float4*>(mean_s);
            float acc = 0.f;
            #pragma unroll 16
            for (int k = 0; k < C_ / 4; ++k) {
                float4 w = wr[k];
                float4 m = ms[k];
                acc = fmaf(m.x, w.x, acc);
                acc = fmaf(m.y, w.y, acc);
                acc = fmaf(m.z, w.z, acc);
                acc = fmaf(m.w, w.w, acc);
            }
            y_s[t] = acc;
        }
        __syncthreads();

        float v = (t < HIDE_) ? w2 * y_s[t] : -INFINITY;
        red[t] = v;
        __syncthreads();
        #pragma unroll
        for (int off = 128; off > 0; off >>= 1) {
            if (t < off) red[t] = fmaxf(red[t], red[t + off]);
            __syncthreads();
        }
        float m = red[0];
        __syncthreads();
        float e = (t < HIDE_) ? __expf(v - m) : 0.f;
        red[t] = e;
        __syncthreads();
        #pragma unroll
        for (int off = 128; off > 0; off >>= 1) {
            if (t < off) red[t] += red[t + off];
            __syncthreads();
        }
        float inv_sum = 1.0f / red[0];
        __syncthreads();

        if (t < HIDE_) {
            float acc = 0.f;
            #pragma unroll 8
            for (int k = 0; k < HIDE_; ++k) acc = fmaf(y_s[k], A2[(size_t)k * HIDE_ + t], acc);
            float y2 = y_s[t] * (e * inv_sum) + acc;
            z_s[t] = fmaxf(w3 * y2, 0.f);
        }
        __syncthreads();

        {
            const float4* wr = reinterpret_cast<const float4*>(w4 + (size_t)t * HIDE_);
            const float4* zs = reinterpret_cast<const float4*>(z_s);
            float acc = 0.f;
            #pragma unroll 16
            for (int k = 0; k < HIDE_ / 4; ++k) {
                float4 w = wr[k];
                float4 z = zs[k];
                acc = fmaf(z.x, w.x, acc);
                acc = fmaf(z.y, w.y, acc);
                acc = fmaf(z.z, w.z, acc);
                acc = fmaf(z.w, w.w, acc);
            }
            g_gate[b * C_ + t] = 1.0f / (1.0f + __expf(-acc));
        }
        __syncthreads();
        if (t == 0) {
            g_cnt[b] = 0;            // self-reset for next replay
            __threadfence();         // release: gate before flag
            g_flag[b] = 1;
        }
    } else {
        // ---------------- scale row (waits briefly on the gate flag) ----------------
        if (t == 0) {
            while (g_flag[b] == 0) __nanosleep(32);
            __threadfence();         // acquire before reading g_gate
        }
        __syncthreads();

        float g = __ldcg(&g_gate[row]);
        const float4* x4 = reinterpret_cast<const float4*>(x) + (size_t)row * HW4_;
        float4* o4 = reinterpret_cast<float4*>(out) + (size_t)row * HW4_;
        #pragma unroll
        for (int i = 0; i < 16; ++i) {
            int idx = t + i * 256;
            float4 v = __ldcg(&x4[idx]);   // expected L2 hit (lag = 2 batches)
            v.x *= g; v.y *= g; v.z *= g; v.w *= g;
            __stcs(&o4[idx], v);           // evict-first: don't displace x
        }

        if (t == 0) {
            int old = atomicAdd(&g_done[b], 1);
            if (old == C_ - 1) {           // last scaler: reset for next replay
                g_done[b] = 0;
                g_flag[b] = 0;
            }
        }
    }
}

extern "C" void kernel_launch(void* const* d_in, const int* in_sizes, int n_in,
                              void* d_out, int out_size) {
    const float* x  = (const float*)d_in[0];
    const float* w1 = (const float*)d_in[1];
    const float* w2 = (const float*)d_in[2];
    const float* w3 = (const float*)d_in[3];
    const float* w4 = (const float*)d_in[4];
    const float* A2 = (const float*)d_in[5];
    float* out = (float*)d_out;

    k_pipe<<<2 * ROWS_, 256>>>(x, w1, w2, w3, w4, A2, out);
}